// round 7
// baseline (speedup 1.0000x reference)
#include <cuda_runtime.h>

// NotearsRKHS on GB300 (sm_103a).
// out[i,j] = sum_l K[j,i,l] * ( alpha[j,l] + 2*sum_{a!=j} beta[j,a,l]*diff[i,l,a] )
// K[j,i,l] = exp(diff[i,l,j]^2 - S[i,l]),  S = full squared distance. GAMMA=1.
// x:[N,D] f32, alpha:[D,N] f32, beta:[D,D,N] f32, out:[N,D] f32. N=2000, D=24.
//
// R6 (resubmit): j-split. 256-thread CTAs; thread t<128 computes j in [0,12)
// for i-row (t), thread t+128 computes j in [12,24) for the same i-row. Halves
// per-thread accumulator/matvec register demand (~100 regs) so occupancy 2x256
// (=16 warps/SM, 4/SMSP) is reached WITHOUT ptxas spills (R5's regression
// cause). All math packed fp32x2 (Blackwell FFMA2, PTX-only). Beta diagonal
// zeroed at smem-load. Deterministic split-l reduction via __device__ partials.

#define NN 2000
#define DD 24
#define BLK 256
#define HALF 128
#define NIB 16            // 16 * 128 = 2048 >= 2000 i-rows
#define LSPLIT 18         // 16 * 18 = 288 CTAs ~ one wave at 148 SM x occ2(256)
#define CHUNK 112         // 18 * 112 = 2016 >= 2000 (tail zero-padded)
#define TL 14             // l-tile in shared
#define NTILES 8          // 112 / 14
#define BROW 580          // padded beta_s row stride (floats), 16B multiple

#define L2E 1.4426950408889634f

__device__ float g_partial[LSPLIT * NN * DD];

typedef unsigned long long u64;

__device__ __forceinline__ u64 pack2(float lo, float hi) {
    u64 r; asm("mov.b64 %0, {%1,%2};" : "=l"(r) : "f"(lo), "f"(hi)); return r;
}
__device__ __forceinline__ void unpack2(u64 v, float& lo, float& hi) {
    asm("mov.b64 {%0,%1}, %2;" : "=f"(lo), "=f"(hi) : "l"(v));
}
__device__ __forceinline__ u64 ffma2(u64 a, u64 b, u64 c) {
    u64 d; asm("fma.rn.f32x2 %0, %1, %2, %3;" : "=l"(d) : "l"(a), "l"(b), "l"(c)); return d;
}
__device__ __forceinline__ u64 add2(u64 a, u64 b) {
    u64 d; asm("add.rn.f32x2 %0, %1, %2;" : "=l"(d) : "l"(a), "l"(b)); return d;
}
__device__ __forceinline__ u64 mul2(u64 a, u64 b) {
    u64 d; asm("mul.rn.f32x2 %0, %1, %2;" : "=l"(d) : "l"(a), "l"(b)); return d;
}
__device__ __forceinline__ float ex2f(float a) {
    float r; asm("ex2.approx.ftz.f32 %0, %1;" : "=f"(r) : "f"(a)); return r;
}

__global__ __launch_bounds__(BLK, 2)
void notears_main(const float* __restrict__ x,
                  const float* __restrict__ alpha,
                  const float* __restrict__ beta)
{
    __shared__ __align__(16) float beta_s[TL * BROW];  // [lt][j*24+a], diag zeroed
    __shared__ __align__(16) float nxl_s[TL * 24];     // negated x[l] tile
    __shared__ __align__(16) float al_s[TL * 24];      // alpha[j,l] tile, [lt][j]

    const int tid = threadIdx.x;
    const int lane_i = tid & (HALF - 1);       // i-row within block
    const int jh = tid >> 7;                   // j-half: 0 -> j[0,12), 1 -> j[12,24)
    const int i = blockIdx.x * HALF + lane_i;
    const int l_base = blockIdx.y * CHUNK;

    const u64 TWO2 = pack2(2.0f, 2.0f);
    const u64 L2E2 = pack2(L2E, L2E);

    // per-thread x row, packed (zeros for tail threads)
    u64 xi2[12];
    {
        const float4* xr = (const float4*)(x + (size_t)i * DD);
        #pragma unroll
        for (int q = 0; q < 6; q++) {
            float4 v = (i < NN) ? xr[q] : make_float4(0.f, 0.f, 0.f, 0.f);
            xi2[2*q]   = pack2(v.x, v.y);
            xi2[2*q+1] = pack2(v.z, v.w);
        }
    }

    u64 acc2[6];   // 12 j's per thread
    #pragma unroll
    for (int p = 0; p < 6; p++) acc2[p] = 0ull;

    for (int tile = 0; tile < NTILES; tile++) {
        const int l0 = l_base + tile * TL;
        __syncthreads();
        // beta tile: beta_s[lt*BROW + ja] = beta[ja*NN + l]; zero-pad l >= NN;
        // zero the (a==j) diagonal here (ja % 25 == 0) so the matvec needs no fixup.
        for (int idx = tid; idx < 576 * (TL / 2); idx += BLK) {
            int ja = idx / (TL / 2);
            int p  = idx - ja * (TL / 2);
            int lt = 2 * p;
            int l  = l0 + lt;
            float2 v;
            if (l + 2 <= NN) {
                v = *(const float2*)(beta + (size_t)ja * NN + l);
            } else {
                v.x = (l     < NN) ? beta[(size_t)ja * NN + l]     : 0.0f;
                v.y = (l + 1 < NN) ? beta[(size_t)ja * NN + l + 1] : 0.0f;
            }
            if (ja % 25 == 0) { v.x = 0.0f; v.y = 0.0f; }   // diagonal beta[j,j,:]
            beta_s[lt * BROW + ja]       = v.x;
            beta_s[(lt + 1) * BROW + ja] = v.y;
        }
        // negated x[l] tile
        for (int idx = tid; idx < TL * 24; idx += BLK) {
            int lt = idx / 24;
            int k  = idx - lt * 24;
            int l  = l0 + lt;
            nxl_s[idx] = (l < NN) ? -x[(size_t)l * DD + k] : 0.0f;
        }
        // alpha tile (zero-pad -> padded l contributes exactly 0)
        for (int idx = tid; idx < TL * 24; idx += BLK) {
            int lt = idx / 24;
            int j  = idx - lt * 24;
            int l  = l0 + lt;
            al_s[lt * 24 + j] = (l < NN) ? alpha[(size_t)j * NN + l] : 0.0f;
        }
        __syncthreads();

        #pragma unroll 1
        for (int lt = 0; lt < TL; lt++) {
            // packed diffs + squared distance S (duplicated across j-halves)
            const ulonglong2* nx2 = (const ulonglong2*)&nxl_s[lt * 24];
            u64 df2[12];
            u64 sa = 0ull, sb = 0ull;
            #pragma unroll
            for (int q = 0; q < 6; q++) {
                ulonglong2 v = nx2[q];
                u64 d0 = add2(xi2[2*q],   v.x); df2[2*q]   = d0; sa = ffma2(d0, d0, sa);
                u64 d1 = add2(xi2[2*q+1], v.y); df2[2*q+1] = d1; sb = ffma2(d1, d1, sb);
            }
            float slo, shi;
            unpack2(add2(sa, sb), slo, shi);
            const float S = slo + shi;
            const float m = -S * L2E;
            const u64 nS2 = pack2(m, m);

            const float* bb   = &beta_s[lt * BROW] + jh * (12 * 24);
            const float* arow = &al_s[lt * 24] + jh * 12;
            const int jpbase = jh * 6;

            #pragma unroll
            for (int jp = 0; jp < 6; jp++) {
                const ulonglong2* b0 = (const ulonglong2*)(bb + (2 * jp) * 24);
                const ulonglong2* b1 = (const ulonglong2*)(bb + (2 * jp + 1) * 24);
                // tt[j] = sum_a beta~[j,a]*diff[a]  (diag already zero)
                u64 t0a = 0ull, t0b = 0ull, t1a = 0ull, t1b = 0ull;
                #pragma unroll
                for (int q = 0; q < 6; q++) {
                    ulonglong2 v0 = b0[q];   // broadcast LDS.128
                    ulonglong2 v1 = b1[q];
                    t0a = ffma2(v0.x, df2[2*q],   t0a);
                    t0b = ffma2(v0.y, df2[2*q+1], t0b);
                    t1a = ffma2(v1.x, df2[2*q],   t1a);
                    t1b = ffma2(v1.y, df2[2*q+1], t1b);
                }
                float l0f, h0f, l1f, h1f;
                unpack2(add2(t0a, t0b), l0f, h0f);
                unpack2(add2(t1a, t1b), l1f, h1f);
                u64 tt2 = pack2(l0f + h0f, l1f + h1f);
                u64 al2 = *(const u64*)(arow + 2 * jp);        // LDS.64 broadcast
                u64 w2  = ffma2(TWO2, tt2, al2);               // alpha + 2*tt
                // K = exp(dj^2 - S) = ex2((dj^2 - S)*log2e), arg <= 0 always
                u64 d2   = df2[jpbase + jp];
                u64 dl2  = mul2(d2, L2E2);
                u64 arg2 = ffma2(d2, dl2, nS2);
                float a0, a1;
                unpack2(arg2, a0, a1);
                u64 ej2 = pack2(ex2f(a0), ex2f(a1));
                acc2[jp] = ffma2(ej2, w2, acc2[jp]);
            }
        }
    }

    // write split-l partials: this thread owns out[i, jh*12 .. jh*12+12)
    if (i < NN) {
        float* dst = &g_partial[((size_t)blockIdx.y * NN + i) * DD + jh * 12];
        #pragma unroll
        for (int q = 0; q < 3; q++) {
            float x0, x1, x2, x3;
            unpack2(acc2[2*q],   x0, x1);
            unpack2(acc2[2*q+1], x2, x3);
            ((float4*)dst)[q] = make_float4(x0, x1, x2, x3);
        }
    }
}

__global__ void notears_reduce(float* __restrict__ out) {
    const int idx = blockIdx.x * blockDim.x + threadIdx.x;   // float2 granularity
    if (idx < NN * DD / 2) {
        const float2* p = (const float2*)g_partial;
        float sx = 0.0f, sy = 0.0f;
        #pragma unroll
        for (int q = 0; q < LSPLIT; q++) {
            float2 v = p[(size_t)q * (NN * DD / 2) + idx];
            sx += v.x; sy += v.y;
        }
        ((float2*)out)[idx] = make_float2(sx, sy);
    }
}

extern "C" void kernel_launch(void* const* d_in, const int* in_sizes, int n_in,
                              void* d_out, int out_size) {
    const float* x     = (const float*)d_in[0];
    const float* alpha = (const float*)d_in[1];
    const float* beta  = (const float*)d_in[2];

    dim3 grid(NIB, LSPLIT);
    notears_main<<<grid, BLK>>>(x, alpha, beta);
    notears_reduce<<<(NN * DD / 2 + 255) / 256, 256>>>((float*)d_out);
}

// round 8
// speedup vs baseline: 1.3313x; 1.3313x over previous
#include <cuda_runtime.h>

// NotearsRKHS on GB300 (sm_103a).
// out[i,j] = sum_l K[j,i,l] * ( alpha[j,l] + 2*sum_{a!=j} beta[j,a,l]*diff[i,l,a] )
// K[j,i,l] = exp(diff[i,l,j]^2 - S[i,l]),  S = full squared distance. GAMMA=1.
// x:[N,D] f32, alpha:[D,N] f32, beta:[D,D,N] f32, out:[N,D] f32. N=2000, D=24.
//
// R7: IPT=2 (beta-row amortization over 2 i-rows — the only measured win),
// occupancy 3 via __launch_bounds__(128,3) (168-reg cap; persistent state 144
// regs fits, unlike R5's 128-cap which spilled). Beta diagonal pre-zeroed in
// smem; 4-chain packed matvec per j-pair; fully packed fp32x2 epilogue with
// ex2.approx. Exact tiling 50x40=2000: no l-guards anywhere in the hot path.

#define NN 2000
#define DD 24
#define BLK 128
#define IPT 2
#define IBLK 256          // i-rows per CTA
#define NIB 8             // 8 * 256 = 2048 >= 2000
#define LSPLIT 50         // 8 * 50 = 400 CTAs ~ one wave at 148 SM x occ3 (444)
#define CHUNK 40          // 50 * 40 = 2000 EXACT (no padding, no guards)
#define TL 20             // l-tile in shared
#define NTILES 2          // 40 / 20
#define BROW 580          // padded beta_s row stride (floats), 16B multiple

#define L2E 1.4426950408889634f

__device__ float g_partial[LSPLIT * NN * DD];

typedef unsigned long long u64;

__device__ __forceinline__ u64 pack2(float lo, float hi) {
    u64 r; asm("mov.b64 %0, {%1,%2};" : "=l"(r) : "f"(lo), "f"(hi)); return r;
}
__device__ __forceinline__ void unpack2(u64 v, float& lo, float& hi) {
    asm("mov.b64 {%0,%1}, %2;" : "=f"(lo), "=f"(hi) : "l"(v));
}
__device__ __forceinline__ u64 ffma2(u64 a, u64 b, u64 c) {
    u64 d; asm("fma.rn.f32x2 %0, %1, %2, %3;" : "=l"(d) : "l"(a), "l"(b), "l"(c)); return d;
}
__device__ __forceinline__ u64 add2(u64 a, u64 b) {
    u64 d; asm("add.rn.f32x2 %0, %1, %2;" : "=l"(d) : "l"(a), "l"(b)); return d;
}
__device__ __forceinline__ u64 mul2(u64 a, u64 b) {
    u64 d; asm("mul.rn.f32x2 %0, %1, %2;" : "=l"(d) : "l"(a), "l"(b)); return d;
}
__device__ __forceinline__ float ex2f(float a) {
    float r; asm("ex2.approx.ftz.f32 %0, %1;" : "=f"(r) : "f"(a)); return r;
}

__global__ __launch_bounds__(BLK, 3)
void notears_main(const float* __restrict__ x,
                  const float* __restrict__ alpha,
                  const float* __restrict__ beta)
{
    __shared__ __align__(16) float beta_s[TL * BROW];  // [lt][j*24+a], diag zeroed
    __shared__ __align__(16) float nxl_s[TL * 24];     // negated x[l] tile
    __shared__ __align__(16) float al_s[TL * 24];      // alpha[j,l] tile, [lt][j]

    const int tid = threadIdx.x;
    const int i0 = blockIdx.x * IBLK + tid;
    const int i1 = i0 + BLK;
    const int l_base = blockIdx.y * CHUNK;

    const u64 TWO2 = pack2(2.0f, 2.0f);
    const u64 L2E2 = pack2(L2E, L2E);

    // per-thread x rows, packed (zeros for tail threads -> dead work, unstored)
    u64 xi2[IPT][12];
    {
        const float4* x0 = (const float4*)(x + (size_t)i0 * DD);
        const float4* x1 = (const float4*)(x + (size_t)i1 * DD);
        #pragma unroll
        for (int q = 0; q < 6; q++) {
            float4 v0 = (i0 < NN) ? x0[q] : make_float4(0.f, 0.f, 0.f, 0.f);
            float4 v1 = (i1 < NN) ? x1[q] : make_float4(0.f, 0.f, 0.f, 0.f);
            xi2[0][2*q]   = pack2(v0.x, v0.y);
            xi2[0][2*q+1] = pack2(v0.z, v0.w);
            xi2[1][2*q]   = pack2(v1.x, v1.y);
            xi2[1][2*q+1] = pack2(v1.z, v1.w);
        }
    }

    u64 acc2[IPT][12];
    #pragma unroll
    for (int r = 0; r < IPT; r++)
        #pragma unroll
        for (int p = 0; p < 12; p++) acc2[r][p] = 0ull;

    for (int tile = 0; tile < NTILES; tile++) {
        const int l0 = l_base + tile * TL;
        __syncthreads();
        // beta tile: beta_s[lt*BROW + ja] = beta[ja*NN + l]; diag (ja%25==0)
        // zeroed so the matvec needs no fixup. No bounds checks: 50*40 = 2000.
        for (int idx = tid; idx < 576 * (TL / 2); idx += BLK) {
            int ja = idx / (TL / 2);
            int p  = idx - ja * (TL / 2);
            int lt = 2 * p;
            float2 v = *(const float2*)(beta + (size_t)ja * NN + l0 + lt);
            if (ja % 25 == 0) { v.x = 0.0f; v.y = 0.0f; }   // beta[j,j,:]
            beta_s[lt * BROW + ja]       = v.x;
            beta_s[(lt + 1) * BROW + ja] = v.y;
        }
        // negated x[l] tile
        for (int idx = tid; idx < TL * 24; idx += BLK) {
            int lt = idx / 24;
            int k  = idx - lt * 24;
            nxl_s[idx] = -x[(size_t)(l0 + lt) * DD + k];
        }
        // alpha tile
        for (int idx = tid; idx < TL * 24; idx += BLK) {
            int lt = idx / 24;
            int j  = idx - lt * 24;
            al_s[lt * 24 + j] = alpha[(size_t)j * NN + l0 + lt];
        }
        __syncthreads();

        #pragma unroll 1
        for (int lt = 0; lt < TL; lt++) {
            // packed diffs + squared distance S for both i-rows
            const ulonglong2* nx2 = (const ulonglong2*)&nxl_s[lt * 24];
            u64 df2[IPT][12];
            u64 sa0 = 0ull, sb0 = 0ull, sa1 = 0ull, sb1 = 0ull;
            #pragma unroll
            for (int q = 0; q < 6; q++) {
                ulonglong2 v = nx2[q];
                u64 d;
                d = add2(xi2[0][2*q],   v.x); df2[0][2*q]   = d; sa0 = ffma2(d, d, sa0);
                d = add2(xi2[1][2*q],   v.x); df2[1][2*q]   = d; sa1 = ffma2(d, d, sa1);
                d = add2(xi2[0][2*q+1], v.y); df2[0][2*q+1] = d; sb0 = ffma2(d, d, sb0);
                d = add2(xi2[1][2*q+1], v.y); df2[1][2*q+1] = d; sb1 = ffma2(d, d, sb1);
            }
            u64 nS2[IPT];
            {
                float lo, hi, m;
                unpack2(add2(sa0, sb0), lo, hi);
                m = -(lo + hi) * L2E;
                nS2[0] = pack2(m, m);
                unpack2(add2(sa1, sb1), lo, hi);
                m = -(lo + hi) * L2E;
                nS2[1] = pack2(m, m);
            }

            const float* bb   = &beta_s[lt * BROW];
            const float* arow = &al_s[lt * 24];

            #pragma unroll
            for (int jp = 0; jp < 12; jp++) {
                const ulonglong2* b0 = (const ulonglong2*)(bb + (2 * jp) * 24);
                const ulonglong2* b1 = (const ulonglong2*)(bb + (2 * jp + 1) * 24);
                // 4 chains: (i-row r) x (j in pair); 12 LDS.128 serve all 4.
                u64 c00 = 0ull, c01 = 0ull, c10 = 0ull, c11 = 0ull;
                #pragma unroll
                for (int q = 0; q < 6; q++) {
                    ulonglong2 v0 = b0[q];
                    ulonglong2 v1 = b1[q];
                    c00 = ffma2(v0.x, df2[0][2*q],   c00);
                    c01 = ffma2(v1.x, df2[0][2*q],   c01);
                    c10 = ffma2(v0.x, df2[1][2*q],   c10);
                    c11 = ffma2(v1.x, df2[1][2*q],   c11);
                    c00 = ffma2(v0.y, df2[0][2*q+1], c00);
                    c01 = ffma2(v1.y, df2[0][2*q+1], c01);
                    c10 = ffma2(v0.y, df2[1][2*q+1], c10);
                    c11 = ffma2(v1.y, df2[1][2*q+1], c11);
                }
                const u64 al2 = *(const u64*)(arow + 2 * jp);   // LDS.64 broadcast

                float lo, hi, t0, t1, a0, a1;
                // i-row 0
                unpack2(c00, lo, hi); t0 = lo + hi;
                unpack2(c01, lo, hi); t1 = lo + hi;
                {
                    u64 w2   = ffma2(TWO2, pack2(t0, t1), al2);     // alpha + 2*tt
                    u64 d2   = df2[0][jp];
                    u64 arg2 = ffma2(d2, mul2(d2, L2E2), nS2[0]);   // (dj^2-S)*log2e
                    unpack2(arg2, a0, a1);
                    u64 ej2  = pack2(ex2f(a0), ex2f(a1));
                    acc2[0][jp] = ffma2(ej2, w2, acc2[0][jp]);
                }
                // i-row 1
                unpack2(c10, lo, hi); t0 = lo + hi;
                unpack2(c11, lo, hi); t1 = lo + hi;
                {
                    u64 w2   = ffma2(TWO2, pack2(t0, t1), al2);
                    u64 d2   = df2[1][jp];
                    u64 arg2 = ffma2(d2, mul2(d2, L2E2), nS2[1]);
                    unpack2(arg2, a0, a1);
                    u64 ej2  = pack2(ex2f(a0), ex2f(a1));
                    acc2[1][jp] = ffma2(ej2, w2, acc2[1][jp]);
                }
            }
        }
    }

    // write split-l partials (deterministic reduction in second kernel)
    const size_t base = (size_t)blockIdx.y * NN;
    if (i0 < NN) {
        float4* dst = (float4*)&g_partial[(base + i0) * DD];
        #pragma unroll
        for (int q = 0; q < 6; q++) {
            float x0, x1, x2, x3;
            unpack2(acc2[0][2*q],   x0, x1);
            unpack2(acc2[0][2*q+1], x2, x3);
            dst[q] = make_float4(x0, x1, x2, x3);
        }
    }
    if (i1 < NN) {
        float4* dst = (float4*)&g_partial[(base + i1) * DD];
        #pragma unroll
        for (int q = 0; q < 6; q++) {
            float x0, x1, x2, x3;
            unpack2(acc2[1][2*q],   x0, x1);
            unpack2(acc2[1][2*q+1], x2, x3);
            dst[q] = make_float4(x0, x1, x2, x3);
        }
    }
}

__global__ void notears_reduce(float* __restrict__ out) {
    const int idx = blockIdx.x * blockDim.x + threadIdx.x;   // float2 granularity
    if (idx < NN * DD / 2) {
        const float2* p = (const float2*)g_partial;
        float sx = 0.0f, sy = 0.0f;
        #pragma unroll
        for (int q = 0; q < LSPLIT; q++) {
            float2 v = p[(size_t)q * (NN * DD / 2) + idx];
            sx += v.x; sy += v.y;
        }
        ((float2*)out)[idx] = make_float2(sx, sy);
    }
}

extern "C" void kernel_launch(void* const* d_in, const int* in_sizes, int n_in,
                              void* d_out, int out_size) {
    const float* x     = (const float*)d_in[0];
    const float* alpha = (const float*)d_in[1];
    const float* beta  = (const float*)d_in[2];

    dim3 grid(NIB, LSPLIT);
    notears_main<<<grid, BLK>>>(x, alpha, beta);
    notears_reduce<<<(NN * DD / 2 + 255) / 256, 256>>>((float*)d_out);
}

// round 12
// speedup vs baseline: 1.4433x; 1.0842x over previous
#include <cuda_runtime.h>

// NotearsRKHS on GB300 (sm_103a).
// out[i,j] = sum_l K[j,i,l] * ( alpha[j,l] + 2*sum_{a!=j} beta[j,a,l]*diff[i,l,a] )
// K[j,i,l] = exp(diff[i,l,j]^2 - S[i,l]),  S = full squared distance. GAMMA=1.
// x:[N,D] f32, alpha:[D,N] f32, beta:[D,D,N] f32, out:[N,D] f32. N=2000, D=24.
//
// R9 (resubmit x3): the wave-quantization fix. Grid = 8 x 37 = 296 CTAs =
// 148 SM x occ2 EXACTLY one wave (R2/R7 ran 400 CTAs -> 2 sequential waves,
// the dominant loss). IPT=2 keeps the measured beta-row amortization;
// launch_bounds(128,2) gives a 256-reg budget (no spills, R5/R7's failure).
// Beta diagonal pre-zeroed in smem; 4-chain packed fp32x2 matvec; packed ex2
// epilogue. Deterministic split-l reduction via __device__ partials.

#define NN 2000
#define DD 24
#define BLK 128
#define IPT 2
#define IBLK 256          // i-rows per CTA
#define NIB 8             // 8 * 256 = 2048 >= 2000
#define LSPLIT 37         // 8 * 37 = 296 CTAs = 148 SM * occ2: ONE exact wave
#define CHUNK 56          // 37 * 56 = 2072 >= 2000 (tail zero-padded at load)
#define TL 14             // l-tile in shared
#define NTILES 4          // 56 / 14
#define BROW 580          // padded beta_s row stride (floats), 16B multiple

#define L2E 1.4426950408889634f

__device__ float g_partial[LSPLIT * NN * DD];

typedef unsigned long long u64;

__device__ __forceinline__ u64 pack2(float lo, float hi) {
    u64 r; asm("mov.b64 %0, {%1,%2};" : "=l"(r) : "f"(lo), "f"(hi)); return r;
}
__device__ __forceinline__ void unpack2(u64 v, float& lo, float& hi) {
    asm("mov.b64 {%0,%1}, %2;" : "=f"(lo), "=f"(hi) : "l"(v));
}
__device__ __forceinline__ u64 ffma2(u64 a, u64 b, u64 c) {
    u64 d; asm("fma.rn.f32x2 %0, %1, %2, %3;" : "=l"(d) : "l"(a), "l"(b), "l"(c)); return d;
}
__device__ __forceinline__ u64 add2(u64 a, u64 b) {
    u64 d; asm("add.rn.f32x2 %0, %1, %2;" : "=l"(d) : "l"(a), "l"(b)); return d;
}
__device__ __forceinline__ u64 mul2(u64 a, u64 b) {
    u64 d; asm("mul.rn.f32x2 %0, %1, %2;" : "=l"(d) : "l"(a), "l"(b)); return d;
}
__device__ __forceinline__ float ex2f(float a) {
    float r; asm("ex2.approx.ftz.f32 %0, %1;" : "=f"(r) : "f"(a)); return r;
}

__global__ __launch_bounds__(BLK, 2)
void notears_main(const float* __restrict__ x,
                  const float* __restrict__ alpha,
                  const float* __restrict__ beta)
{
    __shared__ __align__(16) float beta_s[TL * BROW];  // [lt][j*24+a], diag zeroed
    __shared__ __align__(16) float nxl_s[TL * 24];     // negated x[l] tile
    __shared__ __align__(16) float al_s[TL * 24];      // alpha[j,l] tile, [lt][j]

    const int tid = threadIdx.x;
    const int i0 = blockIdx.x * IBLK + tid;
    const int i1 = i0 + BLK;
    const int l_base = blockIdx.y * CHUNK;

    const u64 TWO2 = pack2(2.0f, 2.0f);
    const u64 L2E2 = pack2(L2E, L2E);

    // per-thread x rows, packed (zeros for tail threads -> dead work, unstored)
    u64 xi2[IPT][12];
    {
        const float4* x0 = (const float4*)(x + (size_t)i0 * DD);
        const float4* x1 = (const float4*)(x + (size_t)i1 * DD);
        #pragma unroll
        for (int q = 0; q < 6; q++) {
            float4 v0 = (i0 < NN) ? x0[q] : make_float4(0.f, 0.f, 0.f, 0.f);
            float4 v1 = (i1 < NN) ? x1[q] : make_float4(0.f, 0.f, 0.f, 0.f);
            xi2[0][2*q]   = pack2(v0.x, v0.y);
            xi2[0][2*q+1] = pack2(v0.z, v0.w);
            xi2[1][2*q]   = pack2(v1.x, v1.y);
            xi2[1][2*q+1] = pack2(v1.z, v1.w);
        }
    }

    u64 acc2[IPT][12];
    #pragma unroll
    for (int r = 0; r < IPT; r++)
        #pragma unroll
        for (int p = 0; p < 12; p++) acc2[r][p] = 0ull;

    for (int tile = 0; tile < NTILES; tile++) {
        const int l0 = l_base + tile * TL;
        __syncthreads();
        // beta tile: beta_s[lt*BROW + ja] = beta[ja*NN + l]; zero-pad l >= NN;
        // zero the (a==j) diagonal (ja % 25 == 0) so the matvec needs no fixup.
        for (int idx = tid; idx < 576 * (TL / 2); idx += BLK) {
            int ja = idx / (TL / 2);
            int p  = idx - ja * (TL / 2);
            int lt = 2 * p;
            int l  = l0 + lt;
            float2 v;
            if (l + 2 <= NN) {
                v = *(const float2*)(beta + (size_t)ja * NN + l);
            } else {
                v.x = (l     < NN) ? beta[(size_t)ja * NN + l]     : 0.0f;
                v.y = (l + 1 < NN) ? beta[(size_t)ja * NN + l + 1] : 0.0f;
            }
            if (ja % 25 == 0) { v.x = 0.0f; v.y = 0.0f; }   // beta[j,j,:]
            beta_s[lt * BROW + ja]       = v.x;
            beta_s[(lt + 1) * BROW + ja] = v.y;
        }
        // negated x[l] tile
        for (int idx = tid; idx < TL * 24; idx += BLK) {
            int lt = idx / 24;
            int k  = idx - lt * 24;
            int l  = l0 + lt;
            nxl_s[idx] = (l < NN) ? -x[(size_t)l * DD + k] : 0.0f;
        }
        // alpha tile (zero-pad -> padded l contributes exactly 0)
        for (int idx = tid; idx < TL * 24; idx += BLK) {
            int lt = idx / 24;
            int j  = idx - lt * 24;
            int l  = l0 + lt;
            al_s[lt * 24 + j] = (l < NN) ? alpha[(size_t)j * NN + l] : 0.0f;
        }
        __syncthreads();

        #pragma unroll 1
        for (int lt = 0; lt < TL; lt++) {
            // packed diffs + squared distance S for both i-rows
            const ulonglong2* nx2 = (const ulonglong2*)&nxl_s[lt * 24];
            u64 df2[IPT][12];
            u64 sa0 = 0ull, sb0 = 0ull, sa1 = 0ull, sb1 = 0ull;
            #pragma unroll
            for (int q = 0; q < 6; q++) {
                ulonglong2 v = nx2[q];
                u64 d;
                d = add2(xi2[0][2*q],   v.x); df2[0][2*q]   = d; sa0 = ffma2(d, d, sa0);
                d = add2(xi2[1][2*q],   v.x); df2[1][2*q]   = d; sa1 = ffma2(d, d, sa1);
                d = add2(xi2[0][2*q+1], v.y); df2[0][2*q+1] = d; sb0 = ffma2(d, d, sb0);
                d = add2(xi2[1][2*q+1], v.y); df2[1][2*q+1] = d; sb1 = ffma2(d, d, sb1);
            }
            u64 nS2[IPT];
            {
                float lo, hi, m;
                unpack2(add2(sa0, sb0), lo, hi);
                m = -(lo + hi) * L2E;
                nS2[0] = pack2(m, m);
                unpack2(add2(sa1, sb1), lo, hi);
                m = -(lo + hi) * L2E;
                nS2[1] = pack2(m, m);
            }

            const float* bb   = &beta_s[lt * BROW];
            const float* arow = &al_s[lt * 24];

            #pragma unroll
            for (int jp = 0; jp < 12; jp++) {
                const ulonglong2* b0 = (const ulonglong2*)(bb + (2 * jp) * 24);
                const ulonglong2* b1 = (const ulonglong2*)(bb + (2 * jp + 1) * 24);
                // 4 chains: (i-row r) x (j in pair); 12 LDS.128 serve all 4.
                u64 c00 = 0ull, c01 = 0ull, c10 = 0ull, c11 = 0ull;
                #pragma unroll
                for (int q = 0; q < 6; q++) {
                    ulonglong2 v0 = b0[q];
                    ulonglong2 v1 = b1[q];
                    c00 = ffma2(v0.x, df2[0][2*q],   c00);
                    c01 = ffma2(v1.x, df2[0][2*q],   c01);
                    c10 = ffma2(v0.x, df2[1][2*q],   c10);
                    c11 = ffma2(v1.x, df2[1][2*q],   c11);
                    c00 = ffma2(v0.y, df2[0][2*q+1], c00);
                    c01 = ffma2(v1.y, df2[0][2*q+1], c01);
                    c10 = ffma2(v0.y, df2[1][2*q+1], c10);
                    c11 = ffma2(v1.y, df2[1][2*q+1], c11);
                }
                const u64 al2 = *(const u64*)(arow + 2 * jp);   // LDS.64 broadcast

                float lo, hi, t0, t1, a0, a1;
                // i-row 0
                unpack2(c00, lo, hi); t0 = lo + hi;
                unpack2(c01, lo, hi); t1 = lo + hi;
                {
                    u64 w2   = ffma2(TWO2, pack2(t0, t1), al2);     // alpha + 2*tt
                    u64 d2   = df2[0][jp];
                    u64 arg2 = ffma2(d2, mul2(d2, L2E2), nS2[0]);   // (dj^2-S)*log2e
                    unpack2(arg2, a0, a1);
                    u64 ej2  = pack2(ex2f(a0), ex2f(a1));
                    acc2[0][jp] = ffma2(ej2, w2, acc2[0][jp]);
                }
                // i-row 1
                unpack2(c10, lo, hi); t0 = lo + hi;
                unpack2(c11, lo, hi); t1 = lo + hi;
                {
                    u64 w2   = ffma2(TWO2, pack2(t0, t1), al2);
                    u64 d2   = df2[1][jp];
                    u64 arg2 = ffma2(d2, mul2(d2, L2E2), nS2[1]);
                    unpack2(arg2, a0, a1);
                    u64 ej2  = pack2(ex2f(a0), ex2f(a1));
                    acc2[1][jp] = ffma2(ej2, w2, acc2[1][jp]);
                }
            }
        }
    }

    // write split-l partials (deterministic reduction in second kernel)
    const size_t base = (size_t)blockIdx.y * NN;
    if (i0 < NN) {
        float4* dst = (float4*)&g_partial[(base + i0) * DD];
        #pragma unroll
        for (int q = 0; q < 6; q++) {
            float x0, x1, x2, x3;
            unpack2(acc2[0][2*q],   x0, x1);
            unpack2(acc2[0][2*q+1], x2, x3);
            dst[q] = make_float4(x0, x1, x2, x3);
        }
    }
    if (i1 < NN) {
        float4* dst = (float4*)&g_partial[(base + i1) * DD];
        #pragma unroll
        for (int q = 0; q < 6; q++) {
            float x0, x1, x2, x3;
            unpack2(acc2[1][2*q],   x0, x1);
            unpack2(acc2[1][2*q+1], x2, x3);
            dst[q] = make_float4(x0, x1, x2, x3);
        }
    }
}

__global__ void notears_reduce(float* __restrict__ out) {
    const int idx = blockIdx.x * blockDim.x + threadIdx.x;   // float2 granularity
    if (idx < NN * DD / 2) {
        const float2* p = (const float2*)g_partial;
        float sx = 0.0f, sy = 0.0f;
        #pragma unroll
        for (int q = 0; q < LSPLIT; q++) {
            float2 v = p[(size_t)q * (NN * DD / 2) + idx];
            sx += v.x; sy += v.y;
        }
        ((float2*)out)[idx] = make_float2(sx, sy);
    }
}

extern "C" void kernel_launch(void* const* d_in, const int* in_sizes, int n_in,
                              void* d_out, int out_size) {
    const float* x     = (const float*)d_in[0];
    const float* alpha = (const float*)d_in[1];
    const float* beta  = (const float*)d_in[2];

    dim3 grid(NIB, LSPLIT);
    notears_main<<<grid, BLK>>>(x, alpha, beta);
    notears_reduce<<<(NN * DD / 2 + 255) / 256, 256>>>((float*)d_out);
}